// round 1
// baseline (speedup 1.0000x reference)
#include <cuda_runtime.h>
#include <cuda_bf16.h>

// DCT2d: per 8x8 block B, C = A * B * A^T.
// x: (32,1,1024,1024) f32, A: (8,8) f32, out: (32, 16384, 8, 8) f32.
//
// CTA = one block-row strip (8 rows x 1024 cols) of one image: 128 blocks.
// 256 threads: thread t -> block bw = t>>1, output-row half h = t&1 (rows 4h..4h+3).
// Stage 1: U = A @ B   (stream B rows from gmem, scalar-broadcast A from smem)
// Stage 2: C = U @ A^T (vector LDS of A rows)

#define NH 128           // block rows per image
#define NW 128           // block cols per image
#define W  1024

__global__ __launch_bounds__(256, 2)
void dct2d_kernel(const float* __restrict__ x,
                  const float* __restrict__ A,
                  float* __restrict__ out)
{
    __shared__ float As[64];

    const int t = threadIdx.x;
    if (t < 64) As[t] = A[t];
    __syncthreads();

    const int cta = blockIdx.x;
    const int n   = cta >> 7;        // image index
    const int bh  = cta & 127;       // block-row index
    const int bw  = t >> 1;          // block-col index (0..127)
    const int h   = t & 1;           // output-row half (0 or 1)

    const float* row0 = x + (size_t)n * (W * W) + (size_t)(bh * 8) * W + bw * 8;

    // ---- Stage 1: U[r][l] = sum_j A[4h+r][j] * B[j][l], r=0..3 ----
    float U[4][8];
    #pragma unroll
    for (int r = 0; r < 4; ++r)
        #pragma unroll
        for (int l = 0; l < 8; ++l)
            U[r][l] = 0.0f;

    #pragma unroll
    for (int j = 0; j < 8; ++j) {
        const float4 b0 = *reinterpret_cast<const float4*>(row0 + j * W);
        const float4 b1 = *reinterpret_cast<const float4*>(row0 + j * W + 4);
        float B[8] = {b0.x, b0.y, b0.z, b0.w, b1.x, b1.y, b1.z, b1.w};

        #pragma unroll
        for (int r = 0; r < 4; ++r) {
            const float a = As[(4 * h + r) * 8 + j];  // broadcast LDS
            #pragma unroll
            for (int l = 0; l < 8; ++l)
                U[r][l] = fmaf(a, B[l], U[r][l]);
        }
    }

    // ---- Stage 2: C[r][m] = sum_l U[r][l] * A[m][l] ----
    float C[4][8];
    #pragma unroll
    for (int m = 0; m < 8; ++m) {
        const float4 a0 = *reinterpret_cast<const float4*>(&As[m * 8]);
        const float4 a1 = *reinterpret_cast<const float4*>(&As[m * 8 + 4]);
        const float ar[8] = {a0.x, a0.y, a0.z, a0.w, a1.x, a1.y, a1.z, a1.w};

        #pragma unroll
        for (int r = 0; r < 4; ++r) {
            float s = U[r][0] * ar[0];
            #pragma unroll
            for (int l = 1; l < 8; ++l)
                s = fmaf(U[r][l], ar[l], s);
            C[r][m] = s;
        }
    }

    // ---- Store: block (n, bh*128+bw), rows 4h..4h+3, contiguous 64 floats/block ----
    float* ob = out + ((size_t)(n * (NH * NW) + bh * NW + bw)) * 64 + h * 32;
    #pragma unroll
    for (int r = 0; r < 4; ++r) {
        *reinterpret_cast<float4*>(ob + r * 8)     = make_float4(C[r][0], C[r][1], C[r][2], C[r][3]);
        *reinterpret_cast<float4*>(ob + r * 8 + 4) = make_float4(C[r][4], C[r][5], C[r][6], C[r][7]);
    }
}

extern "C" void kernel_launch(void* const* d_in, const int* in_sizes, int n_in,
                              void* d_out, int out_size)
{
    const float* x = (const float*)d_in[0];
    const float* A = (const float*)d_in[1];
    float* out     = (float*)d_out;

    dim3 grid(32 * NH);   // 4096 CTAs: one per (image, block-row)
    dim3 block(256);
    dct2d_kernel<<<grid, block>>>(x, A, out);
}